// round 6
// baseline (speedup 1.0000x reference)
#include <cuda_runtime.h>
#include <cuda_bf16.h>
#include <cstdint>
#include <cstddef>

#define NWSEQ 1024
#define TW    64
#define MWORD (NWSEQ*TW)
#define NDOC  32
#define TSENT 32
#define MSENT (NDOC*TSENT)
#define HD2   512
#define HD3   768
#define EDIM  200

typedef unsigned long long ull;

// scratch (device globals; allocation-free rule)
__device__ float g_xg [2ull*MWORD*HD3];     // word input gates; later partial scores
__device__ float g_h  [(size_t)MWORD*HD2];  // word BiGRU hidden
__device__ float g_sents[(size_t)MSENT*HD2];
__device__ float g_xg2[2ull*MSENT*HD3];
__device__ float g_h2 [(size_t)MSENT*HD2];
__device__ float4 g_whp [2*256*256 + 1024]; // repacked word Wh [dir][k][j]{r,z,n,0} + ring pad
__device__ float4 g_whp2[2*256*256 + 1024];

__device__ __forceinline__ ull pk2(float lo, float hi){
    ull r; asm("mov.b64 %0, {%1,%2};" : "=l"(r) : "f"(lo), "f"(hi)); return r;
}
__device__ __forceinline__ float2 upk2(ull v){
    float2 f; asm("mov.b64 {%0,%1}, %2;" : "=f"(f.x), "=f"(f.y) : "l"(v)); return f;
}
__device__ __forceinline__ ull fma2(ull a, ull b, ull c){
    ull d; asm("fma.rn.f32x2 %0, %1, %2, %3;" : "=l"(d) : "l"(a), "l"(b), "l"(c)); return d;
}
__device__ __forceinline__ float fsig(float x){ return 1.0f/(1.0f + __expf(-x)); }
__device__ __forceinline__ float ftanh(float x){ return 1.0f - 2.0f/(__expf(2.0f*x) + 1.0f); }

// ---- bf16 split helpers ----
__device__ __forceinline__ void cvt_pair(float a, float b, uint32_t& hi, uint32_t& lo){
    __nv_bfloat16 ha = __float2bfloat16_rn(a), hb = __float2bfloat16_rn(b);
    float la = a - __bfloat162float(ha);
    float lb = b - __bfloat162float(hb);
    __nv_bfloat162 ph = __halves2bfloat162(ha, hb);
    __nv_bfloat162 pl = __halves2bfloat162(__float2bfloat16_rn(la), __float2bfloat16_rn(lb));
    hi = *(uint32_t*)&ph; lo = *(uint32_t*)&pl;
}
__device__ __forceinline__ void ldsm4(uint32_t& r0, uint32_t& r1, uint32_t& r2, uint32_t& r3, uint32_t addr){
    asm volatile("ldmatrix.sync.aligned.m8n8.x4.shared.b16 {%0,%1,%2,%3}, [%4];"
        : "=r"(r0), "=r"(r1), "=r"(r2), "=r"(r3) : "r"(addr));
}
__device__ __forceinline__ void ldsm2t(uint32_t& r0, uint32_t& r1, uint32_t addr){
    asm volatile("ldmatrix.sync.aligned.m8n8.x2.trans.shared.b16 {%0,%1}, [%2];"
        : "=r"(r0), "=r"(r1) : "r"(addr));
}
__device__ __forceinline__ void mma16816(float* d, uint32_t a0, uint32_t a1, uint32_t a2, uint32_t a3,
                                         uint32_t b0, uint32_t b1){
    asm volatile("mma.sync.aligned.m16n8k16.row.col.f32.bf16.bf16.f32 "
        "{%0,%1,%2,%3}, {%4,%5,%6,%7}, {%8,%9}, {%0,%1,%2,%3};"
        : "+f"(d[0]), "+f"(d[1]), "+f"(d[2]), "+f"(d[3])
        : "r"(a0), "r"(a1), "r"(a2), "r"(a3), "r"(b0), "r"(b1));
}

// ---------------------------------------------------------------------------
// Repack Wh [256][768] -> float4[dir][k][j] = {Wr, Wz, Wn, 0}
// ---------------------------------------------------------------------------
__global__ void repack_wh_kernel(const float* __restrict__ Whf,
                                 const float* __restrict__ Whb,
                                 float4* __restrict__ whp){
    int k = blockIdx.x, d = blockIdx.y, j = threadIdx.x;
    const float* Wh = d ? Whb : Whf;
    float4 v;
    v.x = Wh[(size_t)k*HD3 + j];
    v.y = Wh[(size_t)k*HD3 + 256 + j];
    v.z = Wh[(size_t)k*HD3 + 512 + j];
    v.w = 0.f;
    whp[((size_t)d*256 + k)*256 + j] = v;
}

// ---------------------------------------------------------------------------
// bf16-split tensor-core GEMM. Block tile 128(M) x 64(N), k-tile 32.
// 8 warps: warp w computes rows [16w,16w+16), all 64 cols.
//  SCORE=0: out[dir][m][j] = A[row(m)] @ W_dir + bias_dir  (ldw = nyPerDir*64)
//  SCORE=1: out[jb*M + m] = sum_j tanh((A@W+b)[m][j])*ctx[j] over this tile's 64 j
// grid = (M/128, (SCORE?1:2)*nyPerDir)
// ---------------------------------------------------------------------------
#define ASTR 40   // ushorts per A smem row (32 + pad)
#define BSTR 72   // ushorts per B smem row (64 + pad)
template<bool SCORE>
__global__ __launch_bounds__(256,2) void mma_gemm_kernel(
    const float* __restrict__ A, const int* __restrict__ gather, int K,
    const float* __restrict__ Wf, const float* __restrict__ Wb,
    const float* __restrict__ bf_, const float* __restrict__ bb_,
    const float* __restrict__ ctx,
    float* __restrict__ out, int M, int nyPerDir)
{
    __shared__ __align__(16) unsigned short sAhi[128*ASTR], sAlo[128*ASTR];
    __shared__ __align__(16) unsigned short sBhi[32*BSTR],  sBlo[32*BSTR];
    int tid = threadIdx.x;
    int w = tid >> 5, lane = tid & 31;
    int g = lane >> 2, t4 = lane & 3;
    int m0 = blockIdx.x * 128;
    int dir = blockIdx.y / nyPerDir;
    int jb  = blockIdx.y % nyPerDir;
    int j0  = jb * 64;
    int ldw = nyPerDir * 64;
    const float* W    = dir ? Wb : Wf;
    const float* bias = dir ? bb_ : bf_;

    // loaders
    int arow = tid >> 1, ahalf = tid & 1;
    int ridx = m0 + arow;
    const float* ap = A + (size_t)(gather ? gather[ridx] : ridx) * K;   // FIXED: no ahalf offset here
    int bkr = tid >> 3, bc0 = (tid & 7) * 8;
    const float* bp = W + (size_t)bkr * ldw + j0 + bc0;

    float acc[8][4];
#pragma unroll
    for (int n = 0; n < 8; n++){ acc[n][0]=acc[n][1]=acc[n][2]=acc[n][3]=0.f; }

    uint32_t sAhiB = (uint32_t)__cvta_generic_to_shared(sAhi);
    uint32_t sAloB = (uint32_t)__cvta_generic_to_shared(sAlo);
    uint32_t sBhiB = (uint32_t)__cvta_generic_to_shared(sBhi);
    uint32_t sBloB = (uint32_t)__cvta_generic_to_shared(sBlo);
    uint32_t aOff = ((w*16 + (lane & 15)) * ASTR + (lane >> 4) * 8) * 2;
    uint32_t bOff = ((lane & 15) * BSTR) * 2;

    int nt = (K + 31) / 32;
    float ar[16], br[8];

    // preload tile 0
    {
#pragma unroll
        for (int q = 0; q < 4; q++){
            int kk = ahalf*16 + q*4;
            if (kk + 3 < K) { float4 f = *(const float4*)&ap[kk];
                ar[q*4]=f.x; ar[q*4+1]=f.y; ar[q*4+2]=f.z; ar[q*4+3]=f.w; }
            else {
#pragma unroll
                for (int e = 0; e < 4; e++) ar[q*4+e] = (kk+e < K) ? ap[kk+e] : 0.f;
            }
        }
        if (bkr < K){ float4 f0 = *(const float4*)&bp[0]; float4 f1 = *(const float4*)&bp[4];
            br[0]=f0.x;br[1]=f0.y;br[2]=f0.z;br[3]=f0.w;br[4]=f1.x;br[5]=f1.y;br[6]=f1.z;br[7]=f1.w; }
        else { for (int e=0;e<8;e++) br[e]=0.f; }
    }

    for (int t = 0; t < nt; t++) {
        __syncthreads();
        // convert + store to smem
        {
            int abase = arow * ASTR + ahalf * 16;
#pragma unroll
            for (int p = 0; p < 8; p++){
                uint32_t hi, lo;
                cvt_pair(ar[2*p], ar[2*p+1], hi, lo);
                *(uint32_t*)&sAhi[abase + 2*p] = hi;
                *(uint32_t*)&sAlo[abase + 2*p] = lo;
            }
            int bbase = bkr * BSTR + bc0;
#pragma unroll
            for (int p = 0; p < 4; p++){
                uint32_t hi, lo;
                cvt_pair(br[2*p], br[2*p+1], hi, lo);
                *(uint32_t*)&sBhi[bbase + 2*p] = hi;
                *(uint32_t*)&sBlo[bbase + 2*p] = lo;
            }
        }
        __syncthreads();
        // prefetch next tile
        if (t + 1 < nt) {
            int k0 = (t + 1) * 32;
#pragma unroll
            for (int q = 0; q < 4; q++){
                int kk = k0 + ahalf*16 + q*4;
                if (kk + 3 < K) { float4 f = *(const float4*)&ap[kk];
                    ar[q*4]=f.x; ar[q*4+1]=f.y; ar[q*4+2]=f.z; ar[q*4+3]=f.w; }
                else {
#pragma unroll
                    for (int e = 0; e < 4; e++) ar[q*4+e] = (kk+e < K) ? ap[kk+e] : 0.f;
                }
            }
            if (k0 + bkr < K){ const float* b2 = bp + (size_t)k0 * ldw;
                float4 f0 = *(const float4*)&b2[0]; float4 f1 = *(const float4*)&b2[4];
                br[0]=f0.x;br[1]=f0.y;br[2]=f0.z;br[3]=f0.w;br[4]=f1.x;br[5]=f1.y;br[6]=f1.z;br[7]=f1.w; }
            else { for (int e=0;e<8;e++) br[e]=0.f; }
        }
        // mma on current smem tile: two k16 halves
#pragma unroll
        for (int h = 0; h < 2; h++){
            uint32_t ah0,ah1,ah2,ah3, al0,al1,al2,al3;
            ldsm4(ah0,ah1,ah2,ah3, sAhiB + aOff + h*32);
            ldsm4(al0,al1,al2,al3, sAloB + aOff + h*32);
#pragma unroll
            for (int n = 0; n < 8; n++){
                uint32_t bh0,bh1, bl0,bl1;
                uint32_t ba = bOff + h*16*BSTR*2 + n*16;
                ldsm2t(bh0,bh1, sBhiB + ba);
                ldsm2t(bl0,bl1, sBloB + ba);
                mma16816(acc[n], ah0,ah1,ah2,ah3, bh0,bh1);
                mma16816(acc[n], ah0,ah1,ah2,ah3, bl0,bl1);
                mma16816(acc[n], al0,al1,al2,al3, bh0,bh1);
            }
        }
    }

    // epilogue
    if (!SCORE) {
        float* od = out + (size_t)dir * M * ldw;
        int r0 = m0 + w*16 + g;
#pragma unroll
        for (int n = 0; n < 8; n++){
            int c = j0 + n*8 + t4*2;
            float b0 = __ldg(&bias[c]), b1 = __ldg(&bias[c+1]);
            float2 o0{acc[n][0] + b0, acc[n][1] + b1};
            float2 o1{acc[n][2] + b0, acc[n][3] + b1};
            *(float2*)&od[(size_t)r0 * ldw + c]       = o0;
            *(float2*)&od[(size_t)(r0+8) * ldw + c]   = o1;
        }
    } else {
        float s0 = 0.f, s1 = 0.f;
#pragma unroll
        for (int n = 0; n < 8; n++){
            int c = j0 + n*8 + t4*2;
            float b0 = __ldg(&bias[c]), b1 = __ldg(&bias[c+1]);
            float c0 = __ldg(&ctx[c]),  c1 = __ldg(&ctx[c+1]);
            s0 += ftanh(acc[n][0] + b0)*c0 + ftanh(acc[n][1] + b1)*c1;
            s1 += ftanh(acc[n][2] + b0)*c0 + ftanh(acc[n][3] + b1)*c1;
        }
        s0 += __shfl_xor_sync(0xffffffffu, s0, 1); s0 += __shfl_xor_sync(0xffffffffu, s0, 2);
        s1 += __shfl_xor_sync(0xffffffffu, s1, 1); s1 += __shfl_xor_sync(0xffffffffu, s1, 2);
        if (t4 == 0){
            int r0 = m0 + w*16 + g;
            out[(size_t)jb * M + r0]     = s0;
            out[(size_t)jb * M + r0 + 8] = s1;
        }
    }
}

// ---------------------------------------------------------------------------
// GRU scan: G seqs/block, h ping-pong in smem [buf][k][g], h_prev in regs.
// Thread j owns hidden unit j. 4-deep weight prefetch ring. grid = (NS/G)*2.
// ---------------------------------------------------------------------------
template<int T, int G>
__global__ __launch_bounds__(256) void gru_scan_kernel(
    const float* __restrict__ xg,   // [2][NS*T][768]
    float* __restrict__ hout,       // [NS*T][512]
    const float4* __restrict__ whp, // [2][256][256] (+pad)
    const float* __restrict__ bhf, const float* __restrict__ bhb, int NS)
{
    constexpr int P = G / 2;
    __shared__ __align__(16) float sh[2][256][G];
    int j = threadIdx.x;
    int gpd = NS / G;
    int d  = blockIdx.x / gpd;
    int n0 = (blockIdx.x % gpd) * G;
    const float* bh = d ? bhb : bhf;
    const float4* Wp = whp + (size_t)d * 256 * 256;
    const float* xgd = xg + (size_t)d * NS * T * HD3;
    float bhr = bh[j], bhz = bh[256 + j], bhn = bh[512 + j];
    float hprev[G];
#pragma unroll
    for (int gg = 0; gg < G; gg++){ hprev[gg] = 0.f; sh[0][j][gg] = 0.f; }
    __syncthreads();

    int cur = 0;
    for (int tt = 0; tt < T; tt++) {
        int t = d ? (T - 1 - tt) : tt;
        ull ar[P], az[P], an[P];
#pragma unroll
        for (int p = 0; p < P; p++){
            ar[p] = pk2(bhr, bhr); az[p] = pk2(bhz, bhz); an[p] = pk2(bhn, bhn);
        }
        float4 wring[4];
#pragma unroll
        for (int q = 0; q < 4; q++) wring[q] = Wp[(size_t)q * 256 + j];
#pragma unroll 4
        for (int k = 0; k < 256; k++) {
            float4 wv = wring[k & 3];
            wring[k & 3] = Wp[(size_t)(k + 4) * 256 + j];   // ring pad beyond end
            ull wr2 = pk2(wv.x, wv.x), wz2 = pk2(wv.y, wv.y), wn2 = pk2(wv.z, wv.z);
#pragma unroll
            for (int p = 0; p < P; p++){
                ull h2 = *(const ull*)&sh[cur][k][2*p];
                ar[p] = fma2(wr2, h2, ar[p]);
                az[p] = fma2(wz2, h2, az[p]);
                an[p] = fma2(wn2, h2, an[p]);
            }
        }
        int nxt = cur ^ 1;
        float hnew[G];
#pragma unroll
        for (int p = 0; p < P; p++){
            float2 fr = upk2(ar[p]), fz = upk2(az[p]), fn = upk2(an[p]);
#pragma unroll
            for (int e = 0; e < 2; e++){
                int gg = 2*p + e;
                const float* xp = xgd + ((size_t)(n0 + gg) * T + t) * HD3;
                float hr = e ? fr.y : fr.x, hz = e ? fz.y : fz.x, hn = e ? fn.y : fn.x;
                float r = fsig(xp[j] + hr), z = fsig(xp[256 + j] + hz);
                float n = ftanh(xp[512 + j] + r * hn);
                hnew[gg] = (1.f - z) * n + z * hprev[gg];
            }
        }
#pragma unroll
        for (int gg = 0; gg < G; gg++){
            hprev[gg] = hnew[gg];
            sh[nxt][j][gg] = hnew[gg];
            hout[((size_t)(n0 + gg) * T + t) * HD2 + d * 256 + j] = hnew[gg];
        }
        cur = nxt;
        __syncthreads();
    }
}

// ---------------------------------------------------------------------------
// Attention epilogue: sum partial scores -> sparsemax -> weighted sum of h.
// ---------------------------------------------------------------------------
template<int T, bool FINAL>
__global__ __launch_bounds__(256) void attn_epi_kernel(
    const float* __restrict__ part,   // [8][nseq*T] partial scores
    const float* __restrict__ h,      // [nseq*T][512]
    float* __restrict__ outv,
    const float* __restrict__ outW,
    const float* __restrict__ outb,
    float* __restrict__ outFinal,
    int Mtot)
{
    __shared__ float sScore[T], sX[T], sSrt[T], sAtt[T];
    __shared__ float sTau, sMax;
    __shared__ float sDoc[512];
    int tid = threadIdx.x;
    int n = blockIdx.x;
    const float* hbase = h + (size_t)n * T * HD2;

    if (tid < T) {
        float s = 0.f;
#pragma unroll
        for (int jb = 0; jb < 8; jb++) s += part[(size_t)jb * Mtot + n * T + tid];
        sScore[tid] = s;
    }
    __syncthreads();
    if (tid == 0) {
        float mx = sScore[0];
        for (int t = 1; t < T; t++) mx = fmaxf(mx, sScore[t]);
        sMax = mx;
    }
    __syncthreads();
    if (tid < T) {
        float x = sScore[tid] - sMax;
        sX[tid] = x;
        int rank = 0;
        for (int u = 0; u < T; u++){
            float xu = sScore[u] - sMax;
            if (xu > x || (xu == x && u < tid)) rank++;
        }
        sSrt[rank] = x;
    }
    __syncthreads();
    if (tid == 0) {
        float cs = -1.f; int supp = 0; float csAt = 0.f;
        for (int k = 0; k < T; k++){
            cs += sSrt[k];
            if ((float)(k + 1) * sSrt[k] > cs) { supp = k + 1; csAt = cs; }
        }
        sTau = csAt / (float)supp;
    }
    __syncthreads();
    if (tid < T) sAtt[tid] = fmaxf(sX[tid] - sTau, 0.f);
    __syncthreads();
    {
        int jj = tid * 2;
        float ax = 0.f, ay = 0.f;
#pragma unroll 8
        for (int t = 0; t < T; t++){
            float2 hv = *(const float2*)&hbase[(size_t)t * HD2 + jj];
            float a = sAtt[t];
            ax += a * hv.x; ay += a * hv.y;
        }
        if (FINAL){ sDoc[jj] = ax; sDoc[jj + 1] = ay; }
        else { float2 o{ax, ay}; *(float2*)&outv[(size_t)n * HD2 + jj] = o; }
    }
    if (FINAL) {
        __syncthreads();
        if (tid < 10) {
            float s = outb[tid];
            for (int jj2 = 0; jj2 < 512; jj2++) s += sDoc[jj2] * outW[jj2 * 10 + tid];
            outFinal[n * 10 + tid] = s;
        }
    }
}

extern "C" void kernel_launch(void* const* d_in, const int* in_sizes, int n_in,
                              void* d_out, int out_size) {
    const int*   tokens  = (const int*)  d_in[0];
    const float* emb     = (const float*)d_in[1];
    const float* w_Wx_f  = (const float*)d_in[2];
    const float* w_Wh_f  = (const float*)d_in[3];
    const float* w_bx_f  = (const float*)d_in[4];
    const float* w_bh_f  = (const float*)d_in[5];
    const float* w_Wx_b  = (const float*)d_in[6];
    const float* w_Wh_b  = (const float*)d_in[7];
    const float* w_bx_b  = (const float*)d_in[8];
    const float* w_bh_b  = (const float*)d_in[9];
    const float* w_lin_W = (const float*)d_in[10];
    const float* w_lin_b = (const float*)d_in[11];
    const float* w_ctx   = (const float*)d_in[12];
    const float* s_Wx_f  = (const float*)d_in[13];
    const float* s_Wh_f  = (const float*)d_in[14];
    const float* s_bx_f  = (const float*)d_in[15];
    const float* s_bh_f  = (const float*)d_in[16];
    const float* s_Wx_b  = (const float*)d_in[17];
    const float* s_Wh_b  = (const float*)d_in[18];
    const float* s_bx_b  = (const float*)d_in[19];
    const float* s_bh_b  = (const float*)d_in[20];
    const float* s_lin_W = (const float*)d_in[21];
    const float* s_lin_b = (const float*)d_in[22];
    const float* s_ctx   = (const float*)d_in[23];
    const float* out_W   = (const float*)d_in[24];
    const float* out_b   = (const float*)d_in[25];
    float* out = (float*)d_out;

    float *p_xg, *p_h, *p_sents, *p_xg2, *p_h2;
    float4 *p_whp, *p_whp2;
    cudaGetSymbolAddress((void**)&p_xg,   g_xg);
    cudaGetSymbolAddress((void**)&p_h,    g_h);
    cudaGetSymbolAddress((void**)&p_sents,g_sents);
    cudaGetSymbolAddress((void**)&p_xg2,  g_xg2);
    cudaGetSymbolAddress((void**)&p_h2,   g_h2);
    cudaGetSymbolAddress((void**)&p_whp,  g_whp);
    cudaGetSymbolAddress((void**)&p_whp2, g_whp2);

    // 0. repack recurrent weights
    repack_wh_kernel<<<dim3(256,2), 256>>>(w_Wh_f, w_Wh_b, p_whp);
    repack_wh_kernel<<<dim3(256,2), 256>>>(s_Wh_f, s_Wh_b, p_whp2);
    // 1. word input gates (embedding gather fused), both dirs (tensor cores)
    mma_gemm_kernel<false><<<dim3(MWORD/128, 24), 256>>>(
        emb, tokens, EDIM, w_Wx_f, w_Wx_b, w_bx_f, w_bx_b, nullptr, p_xg, MWORD, 12);
    // 2. word BiGRU scan
    gru_scan_kernel<TW, 16><<<(NWSEQ/16)*2, 256>>>(
        p_xg, p_h, p_whp, w_bh_f, w_bh_b, NWSEQ);
    // 3. word rep GEMM fused into scores (tensor cores; partials into g_xg)
    mma_gemm_kernel<true><<<dim3(MWORD/128, 8), 256>>>(
        p_h, nullptr, HD2, w_lin_W, w_lin_W, w_lin_b, w_lin_b, w_ctx, p_xg, MWORD, 8);
    // 4. word attention epilogue -> sentence vectors
    attn_epi_kernel<TW, false><<<NWSEQ, 256>>>(
        p_xg, p_h, p_sents, nullptr, nullptr, nullptr, MWORD);
    // 5. sentence input gates
    mma_gemm_kernel<false><<<dim3(MSENT/128, 24), 256>>>(
        p_sents, nullptr, HD2, s_Wx_f, s_Wx_b, s_bx_f, s_bx_b, nullptr, p_xg2, MSENT, 12);
    // 6. sentence BiGRU scan
    gru_scan_kernel<TSENT, 2><<<(NDOC/2)*2, 256>>>(
        p_xg2, p_h2, p_whp2, s_bh_f, s_bh_b, NDOC);
    // 7. sentence rep+score GEMM (partials into g_xg2)
    mma_gemm_kernel<true><<<dim3(MSENT/128, 8), 256>>>(
        p_h2, nullptr, HD2, s_lin_W, s_lin_W, s_lin_b, s_lin_b, s_ctx, p_xg2, MSENT, 8);
    // 8. sentence attention + final classifier
    attn_epi_kernel<TSENT, true><<<NDOC, 256>>>(
        p_xg2, p_h2, nullptr, out_W, out_b, out, MSENT);
}

// round 7
// speedup vs baseline: 1.3589x; 1.3589x over previous
#include <cuda_runtime.h>
#include <cuda_bf16.h>
#include <cstdint>
#include <cstddef>

#define NWSEQ 1024
#define TW    64
#define MWORD (NWSEQ*TW)
#define NDOC  32
#define TSENT 32
#define MSENT (NDOC*TSENT)
#define HD2   512
#define HD3   768
#define EDIM  200

typedef unsigned long long ull;

// scratch (device globals; allocation-free rule)
__device__ float g_xg [2ull*MWORD*HD3];     // word input gates; later partial scores
__device__ float g_h  [(size_t)MWORD*HD2];  // word BiGRU hidden
__device__ float g_sents[(size_t)MSENT*HD2];
__device__ float g_xg2[2ull*MSENT*HD3];
__device__ float g_h2 [(size_t)MSENT*HD2];
__device__ float4 g_whp [2*256*256 + 1024]; // repacked word Wh [dir][k][j]{r,z,n,0} + prefetch pad
__device__ float4 g_whp2[2*256*256 + 1024];

__device__ __forceinline__ ull pk2(float lo, float hi){
    ull r; asm("mov.b64 %0, {%1,%2};" : "=l"(r) : "f"(lo), "f"(hi)); return r;
}
__device__ __forceinline__ float2 upk2(ull v){
    float2 f; asm("mov.b64 {%0,%1}, %2;" : "=f"(f.x), "=f"(f.y) : "l"(v)); return f;
}
__device__ __forceinline__ ull fma2(ull a, ull b, ull c){
    ull d; asm("fma.rn.f32x2 %0, %1, %2, %3;" : "=l"(d) : "l"(a), "l"(b), "l"(c)); return d;
}
__device__ __forceinline__ float fsig(float x){ return 1.0f/(1.0f + __expf(-x)); }
__device__ __forceinline__ float ftanh(float x){ return 1.0f - 2.0f/(__expf(2.0f*x) + 1.0f); }

// ---- bf16 split helpers ----
__device__ __forceinline__ void cvt_pair(float a, float b, uint32_t& hi, uint32_t& lo){
    __nv_bfloat16 ha = __float2bfloat16_rn(a), hb = __float2bfloat16_rn(b);
    float la = a - __bfloat162float(ha);
    float lb = b - __bfloat162float(hb);
    __nv_bfloat162 ph = __halves2bfloat162(ha, hb);
    __nv_bfloat162 pl = __halves2bfloat162(__float2bfloat16_rn(la), __float2bfloat16_rn(lb));
    hi = *(uint32_t*)&ph; lo = *(uint32_t*)&pl;
}
__device__ __forceinline__ void ldsm4(uint32_t& r0, uint32_t& r1, uint32_t& r2, uint32_t& r3, uint32_t addr){
    asm volatile("ldmatrix.sync.aligned.m8n8.x4.shared.b16 {%0,%1,%2,%3}, [%4];"
        : "=r"(r0), "=r"(r1), "=r"(r2), "=r"(r3) : "r"(addr));
}
__device__ __forceinline__ void ldsm4t(uint32_t& r0, uint32_t& r1, uint32_t& r2, uint32_t& r3, uint32_t addr){
    asm volatile("ldmatrix.sync.aligned.m8n8.x4.trans.shared.b16 {%0,%1,%2,%3}, [%4];"
        : "=r"(r0), "=r"(r1), "=r"(r2), "=r"(r3) : "r"(addr));
}
__device__ __forceinline__ void mma16816(float* d, uint32_t a0, uint32_t a1, uint32_t a2, uint32_t a3,
                                         uint32_t b0, uint32_t b1){
    asm volatile("mma.sync.aligned.m16n8k16.row.col.f32.bf16.bf16.f32 "
        "{%0,%1,%2,%3}, {%4,%5,%6,%7}, {%8,%9}, {%0,%1,%2,%3};"
        : "+f"(d[0]), "+f"(d[1]), "+f"(d[2]), "+f"(d[3])
        : "r"(a0), "r"(a1), "r"(a2), "r"(a3), "r"(b0), "r"(b1));
}

// ---------------------------------------------------------------------------
// Repack Wh [256][768] -> float4[dir][k][j] = {Wr, Wz, Wn, 0}
// ---------------------------------------------------------------------------
__global__ void repack_wh_kernel(const float* __restrict__ Whf,
                                 const float* __restrict__ Whb,
                                 float4* __restrict__ whp){
    int k = blockIdx.x, d = blockIdx.y, j = threadIdx.x;
    const float* Wh = d ? Whb : Whf;
    float4 v;
    v.x = Wh[(size_t)k*HD3 + j];
    v.y = Wh[(size_t)k*HD3 + 256 + j];
    v.z = Wh[(size_t)k*HD3 + 512 + j];
    v.w = 0.f;
    whp[((size_t)d*256 + k)*256 + j] = v;
}

// ---------------------------------------------------------------------------
// bf16-split tensor-core GEMM. Block tile 128(M) x 64(N), k-tile 32.
// 8 warps: warp w computes rows [16w,16w+16), all 64 cols.
// B fragments via ldmatrix.x4.trans (2 n-tiles per instruction).
//  SCORE=0: out[dir][m][j] = A[row(m)] @ W_dir + bias_dir  (ldw = nyPerDir*64)
//  SCORE=1: out[jb*M + m] = sum_j tanh((A@W+b)[m][j])*ctx[j] over this tile's 64 j
// grid = (M/128, (SCORE?1:2)*nyPerDir)
// ---------------------------------------------------------------------------
#define ASTR 40   // ushorts per A smem row (32 + pad)
#define BSTR 72   // ushorts per B smem row (64 + pad)
template<bool SCORE>
__global__ __launch_bounds__(256,2) void mma_gemm_kernel(
    const float* __restrict__ A, const int* __restrict__ gather, int K,
    const float* __restrict__ Wf, const float* __restrict__ Wb,
    const float* __restrict__ bf_, const float* __restrict__ bb_,
    const float* __restrict__ ctx,
    float* __restrict__ out, int M, int nyPerDir)
{
    __shared__ __align__(16) unsigned short sAhi[128*ASTR], sAlo[128*ASTR];
    __shared__ __align__(16) unsigned short sBhi[32*BSTR],  sBlo[32*BSTR];
    int tid = threadIdx.x;
    int w = tid >> 5, lane = tid & 31;
    int g = lane >> 2, t4 = lane & 3;
    int m0 = blockIdx.x * 128;
    int dir = blockIdx.y / nyPerDir;
    int jb  = blockIdx.y % nyPerDir;
    int j0  = jb * 64;
    int ldw = nyPerDir * 64;
    const float* W    = dir ? Wb : Wf;
    const float* bias = dir ? bb_ : bf_;

    // loaders
    int arow = tid >> 1, ahalf = tid & 1;
    int ridx = m0 + arow;
    const float* ap = A + (size_t)(gather ? gather[ridx] : ridx) * K;
    int bkr = tid >> 3, bc0 = (tid & 7) * 8;
    const float* bp = W + (size_t)bkr * ldw + j0 + bc0;

    float acc[8][4];
#pragma unroll
    for (int n = 0; n < 8; n++){ acc[n][0]=acc[n][1]=acc[n][2]=acc[n][3]=0.f; }

    uint32_t sAhiB = (uint32_t)__cvta_generic_to_shared(sAhi);
    uint32_t sAloB = (uint32_t)__cvta_generic_to_shared(sAlo);
    uint32_t sBhiB = (uint32_t)__cvta_generic_to_shared(sBhi);
    uint32_t sBloB = (uint32_t)__cvta_generic_to_shared(sBlo);
    uint32_t aOff = ((w*16 + (lane & 15)) * ASTR + (lane >> 4) * 8) * 2;
    // x4.trans B: lanes 0-7 k-rows 0-7 @ n_even, 8-15 k-rows 8-15 @ n_even,
    //             16-23 k-rows 0-7 @ n_odd, 24-31 k-rows 8-15 @ n_odd
    uint32_t bT = ((lane & 15) * BSTR + (lane >> 4) * 8) * 2;

    int nt = (K + 31) / 32;
    float ar[16], br[8];

    // preload tile 0
    {
#pragma unroll
        for (int q = 0; q < 4; q++){
            int kk = ahalf*16 + q*4;
            if (kk + 3 < K) { float4 f = *(const float4*)&ap[kk];
                ar[q*4]=f.x; ar[q*4+1]=f.y; ar[q*4+2]=f.z; ar[q*4+3]=f.w; }
            else {
#pragma unroll
                for (int e = 0; e < 4; e++) ar[q*4+e] = (kk+e < K) ? ap[kk+e] : 0.f;
            }
        }
        if (bkr < K){ float4 f0 = *(const float4*)&bp[0]; float4 f1 = *(const float4*)&bp[4];
            br[0]=f0.x;br[1]=f0.y;br[2]=f0.z;br[3]=f0.w;br[4]=f1.x;br[5]=f1.y;br[6]=f1.z;br[7]=f1.w; }
        else { for (int e=0;e<8;e++) br[e]=0.f; }
    }

    for (int t = 0; t < nt; t++) {
        __syncthreads();
        // convert + store to smem
        {
            int abase = arow * ASTR + ahalf * 16;
#pragma unroll
            for (int p = 0; p < 8; p++){
                uint32_t hi, lo;
                cvt_pair(ar[2*p], ar[2*p+1], hi, lo);
                *(uint32_t*)&sAhi[abase + 2*p] = hi;
                *(uint32_t*)&sAlo[abase + 2*p] = lo;
            }
            int bbase = bkr * BSTR + bc0;
#pragma unroll
            for (int p = 0; p < 4; p++){
                uint32_t hi, lo;
                cvt_pair(br[2*p], br[2*p+1], hi, lo);
                *(uint32_t*)&sBhi[bbase + 2*p] = hi;
                *(uint32_t*)&sBlo[bbase + 2*p] = lo;
            }
        }
        __syncthreads();
        // prefetch next tile
        if (t + 1 < nt) {
            int k0 = (t + 1) * 32;
#pragma unroll
            for (int q = 0; q < 4; q++){
                int kk = k0 + ahalf*16 + q*4;
                if (kk + 3 < K) { float4 f = *(const float4*)&ap[kk];
                    ar[q*4]=f.x; ar[q*4+1]=f.y; ar[q*4+2]=f.z; ar[q*4+3]=f.w; }
                else {
#pragma unroll
                    for (int e = 0; e < 4; e++) ar[q*4+e] = (kk+e < K) ? ap[kk+e] : 0.f;
                }
            }
            if (k0 + bkr < K){ const float* b2 = bp + (size_t)k0 * ldw;
                float4 f0 = *(const float4*)&b2[0]; float4 f1 = *(const float4*)&b2[4];
                br[0]=f0.x;br[1]=f0.y;br[2]=f0.z;br[3]=f0.w;br[4]=f1.x;br[5]=f1.y;br[6]=f1.z;br[7]=f1.w; }
            else { for (int e=0;e<8;e++) br[e]=0.f; }
        }
        // mma on current smem tile: two k16 halves
#pragma unroll
        for (int h = 0; h < 2; h++){
            uint32_t ah0,ah1,ah2,ah3, al0,al1,al2,al3;
            ldsm4(ah0,ah1,ah2,ah3, sAhiB + aOff + h*32);
            ldsm4(al0,al1,al2,al3, sAloB + aOff + h*32);
#pragma unroll
            for (int np = 0; np < 4; np++){
                uint32_t ba = bT + h*16*BSTR*2 + np*32;
                uint32_t bh0,bh1,bh2,bh3, bl0,bl1,bl2,bl3;
                ldsm4t(bh0,bh1,bh2,bh3, sBhiB + ba);
                ldsm4t(bl0,bl1,bl2,bl3, sBloB + ba);
                mma16816(acc[2*np],   ah0,ah1,ah2,ah3, bh0,bh1);
                mma16816(acc[2*np],   ah0,ah1,ah2,ah3, bl0,bl1);
                mma16816(acc[2*np],   al0,al1,al2,al3, bh0,bh1);
                mma16816(acc[2*np+1], ah0,ah1,ah2,ah3, bh2,bh3);
                mma16816(acc[2*np+1], ah0,ah1,ah2,ah3, bl2,bl3);
                mma16816(acc[2*np+1], al0,al1,al2,al3, bh2,bh3);
            }
        }
    }

    // epilogue
    if (!SCORE) {
        float* od = out + (size_t)dir * M * ldw;
        int r0 = m0 + w*16 + g;
#pragma unroll
        for (int n = 0; n < 8; n++){
            int c = j0 + n*8 + t4*2;
            float b0 = __ldg(&bias[c]), b1 = __ldg(&bias[c+1]);
            float2 o0{acc[n][0] + b0, acc[n][1] + b1};
            float2 o1{acc[n][2] + b0, acc[n][3] + b1};
            *(float2*)&od[(size_t)r0 * ldw + c]       = o0;
            *(float2*)&od[(size_t)(r0+8) * ldw + c]   = o1;
        }
    } else {
        float s0 = 0.f, s1 = 0.f;
#pragma unroll
        for (int n = 0; n < 8; n++){
            int c = j0 + n*8 + t4*2;
            float b0 = __ldg(&bias[c]), b1 = __ldg(&bias[c+1]);
            float c0 = __ldg(&ctx[c]),  c1 = __ldg(&ctx[c+1]);
            s0 += ftanh(acc[n][0] + b0)*c0 + ftanh(acc[n][1] + b1)*c1;
            s1 += ftanh(acc[n][2] + b0)*c0 + ftanh(acc[n][3] + b1)*c1;
        }
        s0 += __shfl_xor_sync(0xffffffffu, s0, 1); s0 += __shfl_xor_sync(0xffffffffu, s0, 2);
        s1 += __shfl_xor_sync(0xffffffffu, s1, 1); s1 += __shfl_xor_sync(0xffffffffu, s1, 2);
        if (t4 == 0){
            int r0 = m0 + w*16 + g;
            out[(size_t)jb * M + r0]     = s0;
            out[(size_t)jb * M + r0 + 8] = s1;
        }
    }
}

// ---------------------------------------------------------------------------
// GRU scan (R4 config: G=8, grid 256, ping-pong h, single-step prefetch).
// Thread j owns hidden unit j. One __syncthreads per step.
// ---------------------------------------------------------------------------
template<int T, int G>
__global__ __launch_bounds__(256) void gru_scan_kernel(
    const float* __restrict__ xg,   // [2][NS*T][768]
    float* __restrict__ hout,       // [NS*T][512]
    const float4* __restrict__ whp, // [2][256][256] (+pad)
    const float* __restrict__ bhf, const float* __restrict__ bhb, int NS)
{
    constexpr int P = G / 2;
    __shared__ __align__(16) float sh[2][256][G];
    int j = threadIdx.x;
    int gpd = NS / G;
    int d  = blockIdx.x / gpd;
    int n0 = (blockIdx.x % gpd) * G;
    const float* bh = d ? bhb : bhf;
    const float4* Wp = whp + (size_t)d * 256 * 256;
    const float* xgd = xg + (size_t)d * NS * T * HD3;
    float bhr = bh[j], bhz = bh[256 + j], bhn = bh[512 + j];
    float hprev[G];
#pragma unroll
    for (int gg = 0; gg < G; gg++){ hprev[gg] = 0.f; sh[0][j][gg] = 0.f; }
    __syncthreads();

    int cur = 0;
    for (int tt = 0; tt < T; tt++) {
        int t = d ? (T - 1 - tt) : tt;
        float xr[G], xz[G], xn[G];
#pragma unroll
        for (int gg = 0; gg < G; gg++) {
            const float* xp = xgd + ((size_t)(n0 + gg) * T + t) * HD3;
            xr[gg] = xp[j]; xz[gg] = xp[256 + j]; xn[gg] = xp[512 + j];
        }
        ull ar[P], az[P], an[P];
#pragma unroll
        for (int p = 0; p < P; p++){
            ar[p] = pk2(bhr, bhr); az[p] = pk2(bhz, bhz); an[p] = pk2(bhn, bhn);
        }
        float4 w = Wp[j];
#pragma unroll 8
        for (int k = 0; k < 256; k++) {
            float4 wnext = Wp[(size_t)(k + 1) * 256 + j];   // pad row beyond end
            ull wr2 = pk2(w.x, w.x), wz2 = pk2(w.y, w.y), wn2 = pk2(w.z, w.z);
#pragma unroll
            for (int p = 0; p < P; p++){
                ull h2 = *(const ull*)&sh[cur][k][2*p];
                ar[p] = fma2(wr2, h2, ar[p]);
                az[p] = fma2(wz2, h2, az[p]);
                an[p] = fma2(wn2, h2, an[p]);
            }
            w = wnext;
        }
        int nxt = cur ^ 1;
        float hnew[G];
#pragma unroll
        for (int p = 0; p < P; p++){
            float2 fr = upk2(ar[p]), fz = upk2(az[p]), fn = upk2(an[p]);
            int g0 = 2*p, g1 = 2*p + 1;
            {
                float r = fsig(xr[g0] + fr.x), z = fsig(xz[g0] + fz.x);
                float n = ftanh(xn[g0] + r * fn.x);
                hnew[g0] = (1.f - z) * n + z * hprev[g0];
            }
            {
                float r = fsig(xr[g1] + fr.y), z = fsig(xz[g1] + fz.y);
                float n = ftanh(xn[g1] + r * fn.y);
                hnew[g1] = (1.f - z) * n + z * hprev[g1];
            }
        }
#pragma unroll
        for (int gg = 0; gg < G; gg++){
            hprev[gg] = hnew[gg];
            sh[nxt][j][gg] = hnew[gg];
            hout[((size_t)(n0 + gg) * T + t) * HD2 + d * 256 + j] = hnew[gg];
        }
        cur = nxt;
        __syncthreads();
    }
}

// ---------------------------------------------------------------------------
// Attention epilogue: sum partial scores -> sparsemax -> weighted sum of h.
// ---------------------------------------------------------------------------
template<int T, bool FINAL>
__global__ __launch_bounds__(256) void attn_epi_kernel(
    const float* __restrict__ part,   // [8][nseq*T] partial scores
    const float* __restrict__ h,      // [nseq*T][512]
    float* __restrict__ outv,
    const float* __restrict__ outW,
    const float* __restrict__ outb,
    float* __restrict__ outFinal,
    int Mtot)
{
    __shared__ float sScore[T], sX[T], sSrt[T], sAtt[T];
    __shared__ float sTau, sMax;
    __shared__ float sDoc[512];
    int tid = threadIdx.x;
    int n = blockIdx.x;
    const float* hbase = h + (size_t)n * T * HD2;

    if (tid < T) {
        float s = 0.f;
#pragma unroll
        for (int jb = 0; jb < 8; jb++) s += part[(size_t)jb * Mtot + n * T + tid];
        sScore[tid] = s;
    }
    __syncthreads();
    if (tid == 0) {
        float mx = sScore[0];
        for (int t = 1; t < T; t++) mx = fmaxf(mx, sScore[t]);
        sMax = mx;
    }
    __syncthreads();
    if (tid < T) {
        float x = sScore[tid] - sMax;
        sX[tid] = x;
        int rank = 0;
        for (int u = 0; u < T; u++){
            float xu = sScore[u] - sMax;
            if (xu > x || (xu == x && u < tid)) rank++;
        }
        sSrt[rank] = x;
    }
    __syncthreads();
    if (tid == 0) {
        float cs = -1.f; int supp = 0; float csAt = 0.f;
        for (int k = 0; k < T; k++){
            cs += sSrt[k];
            if ((float)(k + 1) * sSrt[k] > cs) { supp = k + 1; csAt = cs; }
        }
        sTau = csAt / (float)supp;
    }
    __syncthreads();
    if (tid < T) sAtt[tid] = fmaxf(sX[tid] - sTau, 0.f);
    __syncthreads();
    {
        int jj = tid * 2;
        float ax = 0.f, ay = 0.f;
#pragma unroll 8
        for (int t = 0; t < T; t++){
            float2 hv = *(const float2*)&hbase[(size_t)t * HD2 + jj];
            float a = sAtt[t];
            ax += a * hv.x; ay += a * hv.y;
        }
        if (FINAL){ sDoc[jj] = ax; sDoc[jj + 1] = ay; }
        else { float2 o{ax, ay}; *(float2*)&outv[(size_t)n * HD2 + jj] = o; }
    }
    if (FINAL) {
        __syncthreads();
        if (tid < 10) {
            float s = outb[tid];
            for (int jj2 = 0; jj2 < 512; jj2++) s += sDoc[jj2] * outW[jj2 * 10 + tid];
            outFinal[n * 10 + tid] = s;
        }
    }
}

extern "C" void kernel_launch(void* const* d_in, const int* in_sizes, int n_in,
                              void* d_out, int out_size) {
    const int*   tokens  = (const int*)  d_in[0];
    const float* emb     = (const float*)d_in[1];
    const float* w_Wx_f  = (const float*)d_in[2];
    const float* w_Wh_f  = (const float*)d_in[3];
    const float* w_bx_f  = (const float*)d_in[4];
    const float* w_bh_f  = (const float*)d_in[5];
    const float* w_Wx_b  = (const float*)d_in[6];
    const float* w_Wh_b  = (const float*)d_in[7];
    const float* w_bx_b  = (const float*)d_in[8];
    const float* w_bh_b  = (const float*)d_in[9];
    const float* w_lin_W = (const float*)d_in[10];
    const float* w_lin_b = (const float*)d_in[11];
    const float* w_ctx   = (const float*)d_in[12];
    const float* s_Wx_f  = (const float*)d_in[13];
    const float* s_Wh_f  = (const float*)d_in[14];
    const float* s_bx_f  = (const float*)d_in[15];
    const float* s_bh_f  = (const float*)d_in[16];
    const float* s_Wx_b  = (const float*)d_in[17];
    const float* s_Wh_b  = (const float*)d_in[18];
    const float* s_bx_b  = (const float*)d_in[19];
    const float* s_bh_b  = (const float*)d_in[20];
    const float* s_lin_W = (const float*)d_in[21];
    const float* s_lin_b = (const float*)d_in[22];
    const float* s_ctx   = (const float*)d_in[23];
    const float* out_W   = (const float*)d_in[24];
    const float* out_b   = (const float*)d_in[25];
    float* out = (float*)d_out;

    float *p_xg, *p_h, *p_sents, *p_xg2, *p_h2;
    float4 *p_whp, *p_whp2;
    cudaGetSymbolAddress((void**)&p_xg,   g_xg);
    cudaGetSymbolAddress((void**)&p_h,    g_h);
    cudaGetSymbolAddress((void**)&p_sents,g_sents);
    cudaGetSymbolAddress((void**)&p_xg2,  g_xg2);
    cudaGetSymbolAddress((void**)&p_h2,   g_h2);
    cudaGetSymbolAddress((void**)&p_whp,  g_whp);
    cudaGetSymbolAddress((void**)&p_whp2, g_whp2);

    // 0. repack recurrent weights
    repack_wh_kernel<<<dim3(256,2), 256>>>(w_Wh_f, w_Wh_b, p_whp);
    repack_wh_kernel<<<dim3(256,2), 256>>>(s_Wh_f, s_Wh_b, p_whp2);
    // 1. word input gates (embedding gather fused), both dirs (tensor cores)
    mma_gemm_kernel<false><<<dim3(MWORD/128, 24), 256>>>(
        emb, tokens, EDIM, w_Wx_f, w_Wx_b, w_bx_f, w_bx_b, nullptr, p_xg, MWORD, 12);
    // 2. word BiGRU scan (G=8, grid 256 — measured-best config)
    gru_scan_kernel<TW, 8><<<(NWSEQ/8)*2, 256>>>(
        p_xg, p_h, p_whp, w_bh_f, w_bh_b, NWSEQ);
    // 3. word rep GEMM fused into scores (tensor cores; partials into g_xg)
    mma_gemm_kernel<true><<<dim3(MWORD/128, 8), 256>>>(
        p_h, nullptr, HD2, w_lin_W, w_lin_W, w_lin_b, w_lin_b, w_ctx, p_xg, MWORD, 8);
    // 4. word attention epilogue -> sentence vectors
    attn_epi_kernel<TW, false><<<NWSEQ, 256>>>(
        p_xg, p_h, p_sents, nullptr, nullptr, nullptr, MWORD);
    // 5. sentence input gates
    mma_gemm_kernel<false><<<dim3(MSENT/128, 24), 256>>>(
        p_sents, nullptr, HD2, s_Wx_f, s_Wx_b, s_bx_f, s_bx_b, nullptr, p_xg2, MSENT, 12);
    // 6. sentence BiGRU scan
    gru_scan_kernel<TSENT, 2><<<(NDOC/2)*2, 256>>>(
        p_xg2, p_h2, p_whp2, s_bh_f, s_bh_b, NDOC);
    // 7. sentence rep+score GEMM (partials into g_xg2)
    mma_gemm_kernel<true><<<dim3(MSENT/128, 8), 256>>>(
        p_h2, nullptr, HD2, s_lin_W, s_lin_W, s_lin_b, s_lin_b, s_ctx, p_xg2, MSENT, 8);
    // 8. sentence attention + final classifier
    attn_epi_kernel<TSENT, true><<<NDOC, 256>>>(
        p_xg2, p_h2, nullptr, out_W, out_b, out, MSENT);
}

// round 8
// speedup vs baseline: 1.4810x; 1.0899x over previous
#include <cuda_runtime.h>
#include <cuda_bf16.h>
#include <cstdint>
#include <cstddef>

#define NWSEQ 1024
#define TW    64
#define MWORD (NWSEQ*TW)
#define NDOC  32
#define TSENT 32
#define MSENT (NDOC*TSENT)
#define HD2   512
#define HD3   768
#define EDIM  200

typedef unsigned long long ull;

// scratch (device globals; allocation-free rule)
__device__ float g_xg [2ull*MWORD*HD3];     // word input gates; later partial scores
__device__ float g_h  [(size_t)MWORD*HD2];  // word BiGRU hidden
__device__ float g_sents[(size_t)MSENT*HD2];
__device__ float g_xg2[2ull*MSENT*HD3];
__device__ float g_h2 [(size_t)MSENT*HD2];
__device__ float4 g_whp [2*256*256 + 1024]; // repacked word Wh [dir][k][j]{r,z,n,0} + prefetch pad
__device__ float4 g_whp2[2*256*256 + 1024];

__device__ __forceinline__ ull pk2(float lo, float hi){
    ull r; asm("mov.b64 %0, {%1,%2};" : "=l"(r) : "f"(lo), "f"(hi)); return r;
}
__device__ __forceinline__ float2 upk2(ull v){
    float2 f; asm("mov.b64 {%0,%1}, %2;" : "=f"(f.x), "=f"(f.y) : "l"(v)); return f;
}
__device__ __forceinline__ ull fma2(ull a, ull b, ull c){
    ull d; asm("fma.rn.f32x2 %0, %1, %2, %3;" : "=l"(d) : "l"(a), "l"(b), "l"(c)); return d;
}
__device__ __forceinline__ float fsig(float x){ return 1.0f/(1.0f + __expf(-x)); }
__device__ __forceinline__ float ftanh(float x){ return 1.0f - 2.0f/(__expf(2.0f*x) + 1.0f); }

// ---- bf16 split helpers ----
__device__ __forceinline__ void cvt_pair(float a, float b, uint32_t& hi, uint32_t& lo){
    __nv_bfloat16 ha = __float2bfloat16_rn(a), hb = __float2bfloat16_rn(b);
    float la = a - __bfloat162float(ha);
    float lb = b - __bfloat162float(hb);
    __nv_bfloat162 ph = __halves2bfloat162(ha, hb);
    __nv_bfloat162 pl = __halves2bfloat162(__float2bfloat16_rn(la), __float2bfloat16_rn(lb));
    hi = *(uint32_t*)&ph; lo = *(uint32_t*)&pl;
}
__device__ __forceinline__ void ldsm4(uint32_t& r0, uint32_t& r1, uint32_t& r2, uint32_t& r3, uint32_t addr){
    asm volatile("ldmatrix.sync.aligned.m8n8.x4.shared.b16 {%0,%1,%2,%3}, [%4];"
        : "=r"(r0), "=r"(r1), "=r"(r2), "=r"(r3) : "r"(addr));
}
__device__ __forceinline__ void ldsm4t(uint32_t& r0, uint32_t& r1, uint32_t& r2, uint32_t& r3, uint32_t addr){
    asm volatile("ldmatrix.sync.aligned.m8n8.x4.trans.shared.b16 {%0,%1,%2,%3}, [%4];"
        : "=r"(r0), "=r"(r1), "=r"(r2), "=r"(r3) : "r"(addr));
}
__device__ __forceinline__ void mma16816(float* d, uint32_t a0, uint32_t a1, uint32_t a2, uint32_t a3,
                                         uint32_t b0, uint32_t b1){
    asm volatile("mma.sync.aligned.m16n8k16.row.col.f32.bf16.bf16.f32 "
        "{%0,%1,%2,%3}, {%4,%5,%6,%7}, {%8,%9}, {%0,%1,%2,%3};"
        : "+f"(d[0]), "+f"(d[1]), "+f"(d[2]), "+f"(d[3])
        : "r"(a0), "r"(a1), "r"(a2), "r"(a3), "r"(b0), "r"(b1));
}

// ---------------------------------------------------------------------------
// Repack Wh [256][768] -> float4[dir][k][j] = {Wr, Wz, Wn, 0}
// ---------------------------------------------------------------------------
__global__ void repack_wh_kernel(const float* __restrict__ Whf,
                                 const float* __restrict__ Whb,
                                 float4* __restrict__ whp){
    int k = blockIdx.x, d = blockIdx.y, j = threadIdx.x;
    const float* Wh = d ? Whb : Whf;
    float4 v;
    v.x = Wh[(size_t)k*HD3 + j];
    v.y = Wh[(size_t)k*HD3 + 256 + j];
    v.z = Wh[(size_t)k*HD3 + 512 + j];
    v.w = 0.f;
    whp[((size_t)d*256 + k)*256 + j] = v;
}

// ---------------------------------------------------------------------------
// bf16-split tensor-core GEMM. Block tile 128(M) x 64(N), k-tile 32.
// 8 warps: warp w computes rows [16w,16w+16), all 64 cols.
// B fragments via ldmatrix.x4.trans (2 n-tiles per instruction).
//  SCORE=0: out[dir][m][j] = A[row(m)] @ W_dir + bias_dir  (ldw = nyPerDir*64)
//  SCORE=1: out[jb*M + m] = sum_j tanh((A@W+b)[m][j])*ctx[j] over this tile's 64 j
// grid = (M/128, (SCORE?1:2)*nyPerDir)
// ---------------------------------------------------------------------------
#define ASTR 40   // ushorts per A smem row (32 + pad)
#define BSTR 72   // ushorts per B smem row (64 + pad)
template<bool SCORE>
__global__ __launch_bounds__(256,2) void mma_gemm_kernel(
    const float* __restrict__ A, const int* __restrict__ gather, int K,
    const float* __restrict__ Wf, const float* __restrict__ Wb,
    const float* __restrict__ bf_, const float* __restrict__ bb_,
    const float* __restrict__ ctx,
    float* __restrict__ out, int M, int nyPerDir)
{
    __shared__ __align__(16) unsigned short sAhi[128*ASTR], sAlo[128*ASTR];
    __shared__ __align__(16) unsigned short sBhi[32*BSTR],  sBlo[32*BSTR];
    int tid = threadIdx.x;
    int w = tid >> 5, lane = tid & 31;
    int g = lane >> 2, t4 = lane & 3;
    int m0 = blockIdx.x * 128;
    int dir = blockIdx.y / nyPerDir;
    int jb  = blockIdx.y % nyPerDir;
    int j0  = jb * 64;
    int ldw = nyPerDir * 64;
    const float* W    = dir ? Wb : Wf;
    const float* bias = dir ? bb_ : bf_;

    // loaders
    int arow = tid >> 1, ahalf = tid & 1;
    int ridx = m0 + arow;
    const float* ap = A + (size_t)(gather ? gather[ridx] : ridx) * K;
    int bkr = tid >> 3, bc0 = (tid & 7) * 8;
    const float* bp = W + (size_t)bkr * ldw + j0 + bc0;

    float acc[8][4];
#pragma unroll
    for (int n = 0; n < 8; n++){ acc[n][0]=acc[n][1]=acc[n][2]=acc[n][3]=0.f; }

    uint32_t sAhiB = (uint32_t)__cvta_generic_to_shared(sAhi);
    uint32_t sAloB = (uint32_t)__cvta_generic_to_shared(sAlo);
    uint32_t sBhiB = (uint32_t)__cvta_generic_to_shared(sBhi);
    uint32_t sBloB = (uint32_t)__cvta_generic_to_shared(sBlo);
    uint32_t aOff = ((w*16 + (lane & 15)) * ASTR + (lane >> 4) * 8) * 2;
    uint32_t bT = ((lane & 15) * BSTR + (lane >> 4) * 8) * 2;

    int nt = (K + 31) / 32;
    float ar[16], br[8];

    // preload tile 0
    {
#pragma unroll
        for (int q = 0; q < 4; q++){
            int kk = ahalf*16 + q*4;
            if (kk + 3 < K) { float4 f = *(const float4*)&ap[kk];
                ar[q*4]=f.x; ar[q*4+1]=f.y; ar[q*4+2]=f.z; ar[q*4+3]=f.w; }
            else {
#pragma unroll
                for (int e = 0; e < 4; e++) ar[q*4+e] = (kk+e < K) ? ap[kk+e] : 0.f;
            }
        }
        if (bkr < K){ float4 f0 = *(const float4*)&bp[0]; float4 f1 = *(const float4*)&bp[4];
            br[0]=f0.x;br[1]=f0.y;br[2]=f0.z;br[3]=f0.w;br[4]=f1.x;br[5]=f1.y;br[6]=f1.z;br[7]=f1.w; }
        else { for (int e=0;e<8;e++) br[e]=0.f; }
    }

    for (int t = 0; t < nt; t++) {
        __syncthreads();
        // convert + store to smem
        {
            int abase = arow * ASTR + ahalf * 16;
#pragma unroll
            for (int p = 0; p < 8; p++){
                uint32_t hi, lo;
                cvt_pair(ar[2*p], ar[2*p+1], hi, lo);
                *(uint32_t*)&sAhi[abase + 2*p] = hi;
                *(uint32_t*)&sAlo[abase + 2*p] = lo;
            }
            int bbase = bkr * BSTR + bc0;
#pragma unroll
            for (int p = 0; p < 4; p++){
                uint32_t hi, lo;
                cvt_pair(br[2*p], br[2*p+1], hi, lo);
                *(uint32_t*)&sBhi[bbase + 2*p] = hi;
                *(uint32_t*)&sBlo[bbase + 2*p] = lo;
            }
        }
        __syncthreads();
        // prefetch next tile
        if (t + 1 < nt) {
            int k0 = (t + 1) * 32;
#pragma unroll
            for (int q = 0; q < 4; q++){
                int kk = k0 + ahalf*16 + q*4;
                if (kk + 3 < K) { float4 f = *(const float4*)&ap[kk];
                    ar[q*4]=f.x; ar[q*4+1]=f.y; ar[q*4+2]=f.z; ar[q*4+3]=f.w; }
                else {
#pragma unroll
                    for (int e = 0; e < 4; e++) ar[q*4+e] = (kk+e < K) ? ap[kk+e] : 0.f;
                }
            }
            if (k0 + bkr < K){ const float* b2 = bp + (size_t)k0 * ldw;
                float4 f0 = *(const float4*)&b2[0]; float4 f1 = *(const float4*)&b2[4];
                br[0]=f0.x;br[1]=f0.y;br[2]=f0.z;br[3]=f0.w;br[4]=f1.x;br[5]=f1.y;br[6]=f1.z;br[7]=f1.w; }
            else { for (int e=0;e<8;e++) br[e]=0.f; }
        }
        // mma on current smem tile: two k16 halves
#pragma unroll
        for (int h = 0; h < 2; h++){
            uint32_t ah0,ah1,ah2,ah3, al0,al1,al2,al3;
            ldsm4(ah0,ah1,ah2,ah3, sAhiB + aOff + h*32);
            ldsm4(al0,al1,al2,al3, sAloB + aOff + h*32);
#pragma unroll
            for (int np = 0; np < 4; np++){
                uint32_t ba = bT + h*16*BSTR*2 + np*32;
                uint32_t bh0,bh1,bh2,bh3, bl0,bl1,bl2,bl3;
                ldsm4t(bh0,bh1,bh2,bh3, sBhiB + ba);
                ldsm4t(bl0,bl1,bl2,bl3, sBloB + ba);
                mma16816(acc[2*np],   ah0,ah1,ah2,ah3, bh0,bh1);
                mma16816(acc[2*np],   ah0,ah1,ah2,ah3, bl0,bl1);
                mma16816(acc[2*np],   al0,al1,al2,al3, bh0,bh1);
                mma16816(acc[2*np+1], ah0,ah1,ah2,ah3, bh2,bh3);
                mma16816(acc[2*np+1], ah0,ah1,ah2,ah3, bl2,bl3);
                mma16816(acc[2*np+1], al0,al1,al2,al3, bh2,bh3);
            }
        }
    }

    // epilogue
    if (!SCORE) {
        float* od = out + (size_t)dir * M * ldw;
        int r0 = m0 + w*16 + g;
#pragma unroll
        for (int n = 0; n < 8; n++){
            int c = j0 + n*8 + t4*2;
            float b0 = __ldg(&bias[c]), b1 = __ldg(&bias[c+1]);
            float2 o0{acc[n][0] + b0, acc[n][1] + b1};
            float2 o1{acc[n][2] + b0, acc[n][3] + b1};
            *(float2*)&od[(size_t)r0 * ldw + c]       = o0;
            *(float2*)&od[(size_t)(r0+8) * ldw + c]   = o1;
        }
    } else {
        float s0 = 0.f, s1 = 0.f;
#pragma unroll
        for (int n = 0; n < 8; n++){
            int c = j0 + n*8 + t4*2;
            float b0 = __ldg(&bias[c]), b1 = __ldg(&bias[c+1]);
            float c0 = __ldg(&ctx[c]),  c1 = __ldg(&ctx[c+1]);
            s0 += ftanh(acc[n][0] + b0)*c0 + ftanh(acc[n][1] + b1)*c1;
            s1 += ftanh(acc[n][2] + b0)*c0 + ftanh(acc[n][3] + b1)*c1;
        }
        s0 += __shfl_xor_sync(0xffffffffu, s0, 1); s0 += __shfl_xor_sync(0xffffffffu, s0, 2);
        s1 += __shfl_xor_sync(0xffffffffu, s1, 1); s1 += __shfl_xor_sync(0xffffffffu, s1, 2);
        if (t4 == 0){
            int r0 = m0 + w*16 + g;
            out[(size_t)jb * M + r0]     = s0;
            out[(size_t)jb * M + r0 + 8] = s1;
        }
    }
}

// ---------------------------------------------------------------------------
// GRU scan: G=8 seqs/block, ping-pong h in smem, h_prev in regs.
// x-gate loads AFTER the matvec (keeps k-loop live set small -> <=128 regs,
// 2 blocks/SM, single wave). __launch_bounds__(256,2) enforces the cap.
// ---------------------------------------------------------------------------
template<int T, int G>
__global__ __launch_bounds__(256,2) void gru_scan_kernel(
    const float* __restrict__ xg,   // [2][NS*T][768]
    float* __restrict__ hout,       // [NS*T][512]
    const float4* __restrict__ whp, // [2][256][256] (+pad)
    const float* __restrict__ bhf, const float* __restrict__ bhb, int NS)
{
    constexpr int P = G / 2;
    __shared__ __align__(16) float sh[2][256][G];
    int j = threadIdx.x;
    int gpd = NS / G;
    int d  = blockIdx.x / gpd;
    int n0 = (blockIdx.x % gpd) * G;
    const float* bh = d ? bhb : bhf;
    const float4* Wp = whp + (size_t)d * 256 * 256;
    const float* xgd = xg + (size_t)d * NS * T * HD3;
    float bhr = bh[j], bhz = bh[256 + j], bhn = bh[512 + j];
    float hprev[G];
#pragma unroll
    for (int gg = 0; gg < G; gg++){ hprev[gg] = 0.f; sh[0][j][gg] = 0.f; }
    __syncthreads();

    int cur = 0;
    for (int tt = 0; tt < T; tt++) {
        int t = d ? (T - 1 - tt) : tt;
        ull ar[P], az[P], an[P];
#pragma unroll
        for (int p = 0; p < P; p++){
            ar[p] = pk2(bhr, bhr); az[p] = pk2(bhz, bhz); an[p] = pk2(bhn, bhn);
        }
        float4 w = Wp[j];
#pragma unroll 8
        for (int k = 0; k < 256; k++) {
            float4 wnext = Wp[(size_t)(k + 1) * 256 + j];   // pad row beyond end
            ull wr2 = pk2(w.x, w.x), wz2 = pk2(w.y, w.y), wn2 = pk2(w.z, w.z);
#pragma unroll
            for (int p = 0; p < P; p++){
                ull h2 = *(const ull*)&sh[cur][k][2*p];
                ar[p] = fma2(wr2, h2, ar[p]);
                az[p] = fma2(wz2, h2, az[p]);
                an[p] = fma2(wn2, h2, an[p]);
            }
            w = wnext;
        }
        int nxt = cur ^ 1;
        float hnew[G];
#pragma unroll
        for (int p = 0; p < P; p++){
            float2 fr = upk2(ar[p]), fz = upk2(az[p]), fn = upk2(an[p]);
#pragma unroll
            for (int e = 0; e < 2; e++){
                int gg = 2*p + e;
                const float* xp = xgd + ((size_t)(n0 + gg) * T + t) * HD3;
                float hr = e ? fr.y : fr.x, hz = e ? fz.y : fz.x, hn = e ? fn.y : fn.x;
                float r = fsig(xp[j] + hr), z = fsig(xp[256 + j] + hz);
                float n = ftanh(xp[512 + j] + r * hn);
                hnew[gg] = (1.f - z) * n + z * hprev[gg];
            }
        }
#pragma unroll
        for (int gg = 0; gg < G; gg++){
            hprev[gg] = hnew[gg];
            sh[nxt][j][gg] = hnew[gg];
            hout[((size_t)(n0 + gg) * T + t) * HD2 + d * 256 + j] = hnew[gg];
        }
        cur = nxt;
        __syncthreads();
    }
}

// ---------------------------------------------------------------------------
// Attention epilogue: sum partial scores -> sparsemax -> weighted sum of h.
// ---------------------------------------------------------------------------
template<int T, bool FINAL>
__global__ __launch_bounds__(256) void attn_epi_kernel(
    const float* __restrict__ part,   // [8][nseq*T] partial scores
    const float* __restrict__ h,      // [nseq*T][512]
    float* __restrict__ outv,
    const float* __restrict__ outW,
    const float* __restrict__ outb,
    float* __restrict__ outFinal,
    int Mtot)
{
    __shared__ float sScore[T], sX[T], sSrt[T], sAtt[T];
    __shared__ float sTau, sMax;
    __shared__ float sDoc[512];
    int tid = threadIdx.x;
    int n = blockIdx.x;
    const float* hbase = h + (size_t)n * T * HD2;

    if (tid < T) {
        float s = 0.f;
#pragma unroll
        for (int jb = 0; jb < 8; jb++) s += part[(size_t)jb * Mtot + n * T + tid];
        sScore[tid] = s;
    }
    __syncthreads();
    if (tid == 0) {
        float mx = sScore[0];
        for (int t = 1; t < T; t++) mx = fmaxf(mx, sScore[t]);
        sMax = mx;
    }
    __syncthreads();
    if (tid < T) {
        float x = sScore[tid] - sMax;
        sX[tid] = x;
        int rank = 0;
        for (int u = 0; u < T; u++){
            float xu = sScore[u] - sMax;
            if (xu > x || (xu == x && u < tid)) rank++;
        }
        sSrt[rank] = x;
    }
    __syncthreads();
    if (tid == 0) {
        float cs = -1.f; int supp = 0; float csAt = 0.f;
        for (int k = 0; k < T; k++){
            cs += sSrt[k];
            if ((float)(k + 1) * sSrt[k] > cs) { supp = k + 1; csAt = cs; }
        }
        sTau = csAt / (float)supp;
    }
    __syncthreads();
    if (tid < T) sAtt[tid] = fmaxf(sX[tid] - sTau, 0.f);
    __syncthreads();
    {
        int jj = tid * 2;
        float ax = 0.f, ay = 0.f;
#pragma unroll 8
        for (int t = 0; t < T; t++){
            float2 hv = *(const float2*)&hbase[(size_t)t * HD2 + jj];
            float a = sAtt[t];
            ax += a * hv.x; ay += a * hv.y;
        }
        if (FINAL){ sDoc[jj] = ax; sDoc[jj + 1] = ay; }
        else { float2 o{ax, ay}; *(float2*)&outv[(size_t)n * HD2 + jj] = o; }
    }
    if (FINAL) {
        __syncthreads();
        if (tid < 10) {
            float s = outb[tid];
            for (int jj2 = 0; jj2 < 512; jj2++) s += sDoc[jj2] * outW[jj2 * 10 + tid];
            outFinal[n * 10 + tid] = s;
        }
    }
}

extern "C" void kernel_launch(void* const* d_in, const int* in_sizes, int n_in,
                              void* d_out, int out_size) {
    const int*   tokens  = (const int*)  d_in[0];
    const float* emb     = (const float*)d_in[1];
    const float* w_Wx_f  = (const float*)d_in[2];
    const float* w_Wh_f  = (const float*)d_in[3];
    const float* w_bx_f  = (const float*)d_in[4];
    const float* w_bh_f  = (const float*)d_in[5];
    const float* w_Wx_b  = (const float*)d_in[6];
    const float* w_Wh_b  = (const float*)d_in[7];
    const float* w_bx_b  = (const float*)d_in[8];
    const float* w_bh_b  = (const float*)d_in[9];
    const float* w_lin_W = (const float*)d_in[10];
    const float* w_lin_b = (const float*)d_in[11];
    const float* w_ctx   = (const float*)d_in[12];
    const float* s_Wx_f  = (const float*)d_in[13];
    const float* s_Wh_f  = (const float*)d_in[14];
    const float* s_bx_f  = (const float*)d_in[15];
    const float* s_bh_f  = (const float*)d_in[16];
    const float* s_Wx_b  = (const float*)d_in[17];
    const float* s_Wh_b  = (const float*)d_in[18];
    const float* s_bx_b  = (const float*)d_in[19];
    const float* s_bh_b  = (const float*)d_in[20];
    const float* s_lin_W = (const float*)d_in[21];
    const float* s_lin_b = (const float*)d_in[22];
    const float* s_ctx   = (const float*)d_in[23];
    const float* out_W   = (const float*)d_in[24];
    const float* out_b   = (const float*)d_in[25];
    float* out = (float*)d_out;

    float *p_xg, *p_h, *p_sents, *p_xg2, *p_h2;
    float4 *p_whp, *p_whp2;
    cudaGetSymbolAddress((void**)&p_xg,   g_xg);
    cudaGetSymbolAddress((void**)&p_h,    g_h);
    cudaGetSymbolAddress((void**)&p_sents,g_sents);
    cudaGetSymbolAddress((void**)&p_xg2,  g_xg2);
    cudaGetSymbolAddress((void**)&p_h2,   g_h2);
    cudaGetSymbolAddress((void**)&p_whp,  g_whp);
    cudaGetSymbolAddress((void**)&p_whp2, g_whp2);

    // 0. repack recurrent weights
    repack_wh_kernel<<<dim3(256,2), 256>>>(w_Wh_f, w_Wh_b, p_whp);
    repack_wh_kernel<<<dim3(256,2), 256>>>(s_Wh_f, s_Wh_b, p_whp2);
    // 1. word input gates (embedding gather fused), both dirs (tensor cores)
    mma_gemm_kernel<false><<<dim3(MWORD/128, 24), 256>>>(
        emb, tokens, EDIM, w_Wx_f, w_Wx_b, w_bx_f, w_bx_b, nullptr, p_xg, MWORD, 12);
    // 2. word BiGRU scan (G=8, grid 256, now 2 blocks/SM)
    gru_scan_kernel<TW, 8><<<(NWSEQ/8)*2, 256>>>(
        p_xg, p_h, p_whp, w_bh_f, w_bh_b, NWSEQ);
    // 3. word rep GEMM fused into scores (tensor cores; partials into g_xg)
    mma_gemm_kernel<true><<<dim3(MWORD/128, 8), 256>>>(
        p_h, nullptr, HD2, w_lin_W, w_lin_W, w_lin_b, w_lin_b, w_ctx, p_xg, MWORD, 8);
    // 4. word attention epilogue -> sentence vectors
    attn_epi_kernel<TW, false><<<NWSEQ, 256>>>(
        p_xg, p_h, p_sents, nullptr, nullptr, nullptr, MWORD);
    // 5. sentence input gates
    mma_gemm_kernel<false><<<dim3(MSENT/128, 24), 256>>>(
        p_sents, nullptr, HD2, s_Wx_f, s_Wx_b, s_bx_f, s_bx_b, nullptr, p_xg2, MSENT, 12);
    // 6. sentence BiGRU scan
    gru_scan_kernel<TSENT, 2><<<(NDOC/2)*2, 256>>>(
        p_xg2, p_h2, p_whp2, s_bh_f, s_bh_b, NDOC);
    // 7. sentence rep+score GEMM (partials into g_xg2)
    mma_gemm_kernel<true><<<dim3(MSENT/128, 8), 256>>>(
        p_h2, nullptr, HD2, s_lin_W, s_lin_W, s_lin_b, s_lin_b, s_ctx, p_xg2, MSENT, 8);
    // 8. sentence attention + final classifier
    attn_epi_kernel<TSENT, true><<<NDOC, 256>>>(
        p_xg2, p_h2, nullptr, out_W, out_b, out, MSENT);
}